// round 2
// baseline (speedup 1.0000x reference)
#include <cuda_runtime.h>
#include <math.h>

// Problem dims (fixed by reference)
#define BB   8
#define LL   1024
#define DM   512
#define DI   1024
#define DS   16
#define DTR  32
#define DFF  2048
#define MROWS (BB*LL)   // 8192

// ---------------- scratch (static device globals; no allocation) -------------
__device__ float g_xz  [MROWS * 2 * DI];  // in_proj output: [8192, 2048] (u | z)
__device__ float g_u   [MROWS * DI];      // post conv+silu u
__device__ float g_xdbl[MROWS * 64];      // dt_in(32) | B(16) | C(16)
__device__ float g_dt  [MROWS * DI];      // softplus dt
__device__ float g_y   [MROWS * DI];      // scan output * gate
__device__ float g_r1  [MROWS * DM];      // out_proj + x residual
__device__ float g_h1  [MROWS * DM];      // ln1 output
__device__ float g_ff  [MROWS * DFF];     // gelu(fc1)
__device__ float g_r2  [MROWS * DM];      // fc2 + h1 residual

// ---------------- activation helpers ----------------------------------------
__device__ __forceinline__ float softplus_f(float x) {
    return x > 20.f ? x : log1pf(expf(x));
}
__device__ __forceinline__ float gelu_f(float x) {
    return 0.5f * x * (1.f + erff(x * 0.70710678118654752f));
}

// ---------------- generic SGEMM: C[M,N] = A[M,K] * W[N,K]^T ------------------
// Tiles: 64x64 block, BK=16, 16x16 threads, 4x4 per thread.
// Requires: M % 64 == 0, N % 64 == 0, K % 16 == 0 (true for all calls here).
// Epilogue: optional bias[col], ACT (0 none, 1 softplus, 2 gelu), optional
// residual res[row*ldr + col] added AFTER activation.
template<int ACT>
__global__ void __launch_bounds__(256) gemm64(
    const float* __restrict__ A, int lda,
    const float* __restrict__ W, int K,
    const float* __restrict__ bias,
    const float* __restrict__ res, int ldr,
    float* __restrict__ C, int ldc)
{
    __shared__ float As[16][68];
    __shared__ float Bs[16][68];

    const int tx = threadIdx.x;          // 0..15
    const int ty = threadIdx.y;          // 0..15
    const int tid = ty * 16 + tx;
    const int row0 = blockIdx.y * 64;
    const int col0 = blockIdx.x * 64;

    const int lk = tid & 15;             // k within tile for loads
    const int lm = tid >> 4;             // base m/n for loads (0..15)

    float acc[4][4];
#pragma unroll
    for (int i = 0; i < 4; i++)
#pragma unroll
        for (int j = 0; j < 4; j++) acc[i][j] = 0.f;

    for (int k0 = 0; k0 < K; k0 += 16) {
#pragma unroll
        for (int i = 0; i < 4; i++) {
            int m = lm + i * 16;
            As[lk][m] = A[(size_t)(row0 + m) * lda + k0 + lk];
            Bs[lk][m] = W[(size_t)(col0 + m) * K   + k0 + lk];
        }
        __syncthreads();

#pragma unroll
        for (int kk = 0; kk < 16; kk++) {
            float4 a4 = *reinterpret_cast<const float4*>(&As[kk][ty * 4]);
            float4 b4 = *reinterpret_cast<const float4*>(&Bs[kk][tx * 4]);
            float ra[4] = {a4.x, a4.y, a4.z, a4.w};
            float rb[4] = {b4.x, b4.y, b4.z, b4.w};
#pragma unroll
            for (int i = 0; i < 4; i++)
#pragma unroll
                for (int j = 0; j < 4; j++)
                    acc[i][j] += ra[i] * rb[j];
        }
        __syncthreads();
    }

#pragma unroll
    for (int i = 0; i < 4; i++) {
        int r = row0 + ty * 4 + i;
#pragma unroll
        for (int j = 0; j < 4; j++) {
            int c = col0 + tx * 4 + j;
            float v = acc[i][j];
            if (bias) v += bias[c];
            if (ACT == 1) v = softplus_f(v);
            if (ACT == 2) v = gelu_f(v);
            if (res) v += res[(size_t)r * ldr + c];
            C[(size_t)r * ldc + c] = v;
        }
    }
}

// ---------------- causal depthwise conv (width 4) + bias + SiLU --------------
__global__ void conv_silu_kernel(const float* __restrict__ xz,
                                 const float* __restrict__ cw,
                                 const float* __restrict__ cb,
                                 float* __restrict__ u)
{
    int idx = blockIdx.x * blockDim.x + threadIdx.x;  // over 8192*1024
    int d = idx & (DI - 1);
    int row = idx >> 10;            // b*1024 + l
    int l = row & (LL - 1);
    float sum = cb[d];
#pragma unroll
    for (int j = 0; j < 4; j++) {
        int ll = l - 3 + j;
        if (ll >= 0)
            sum += xz[(size_t)(row - 3 + j) * (2 * DI) + d] * cw[d * 4 + j];
    }
    float sig = 1.f / (1.f + __expf(-sum));
    u[idx] = sum * sig;
}

// ---------------- selective scan ---------------------------------------------
// One thread per (b, d, s). 16 lanes reduce y via shfl.bfly. Lane s==0 applies
// skip (u*D) and gate silu(z) and writes y.
__global__ void __launch_bounds__(256) scan_kernel(
    const float* __restrict__ dt, const float* __restrict__ u,
    const float* __restrict__ xdbl, const float* __restrict__ xz,
    const float* __restrict__ A_log, const float* __restrict__ Dp,
    float* __restrict__ y)
{
    int t = blockIdx.x * blockDim.x + threadIdx.x;
    int chain = t >> 4;                   // (b, d)
    int s = t & 15;
    int b = chain >> 10;
    int d = chain & (DI - 1);

    float a = -expf(A_log[d * DS + s]);
    float Dd = Dp[d];
    float h = 0.f;
    int rb = b << 10;

    for (int l = 0; l < LL; ++l) {
        int row = rb + l;
        float dtv = dt[(size_t)row * DI + d];
        float uv  = u [(size_t)row * DI + d];
        float Bm  = xdbl[(row << 6) + DTR + s];
        float Cm  = xdbl[(row << 6) + DTR + DS + s];

        h = h * __expf(dtv * a) + (dtv * Bm) * uv;
        float p = h * Cm;
        p += __shfl_xor_sync(0xffffffffu, p, 1);
        p += __shfl_xor_sync(0xffffffffu, p, 2);
        p += __shfl_xor_sync(0xffffffffu, p, 4);
        p += __shfl_xor_sync(0xffffffffu, p, 8);
        if (s == 0) {
            float zv = xz[(size_t)row * (2 * DI) + DI + d];
            float sig = 1.f / (1.f + __expf(-zv));
            y[(size_t)row * DI + d] = (p + uv * Dd) * (zv * sig);
        }
    }
}

// ---------------- LayerNorm over 512 cols ------------------------------------
__global__ void __launch_bounds__(128) ln512(
    const float* __restrict__ in, const float* __restrict__ g,
    const float* __restrict__ b, float* __restrict__ out)
{
    int row = blockIdx.x;
    const float* p = in + (size_t)row * DM;
    int tid = threadIdx.x;  // 128
    float v[4], s = 0.f, s2 = 0.f;
#pragma unroll
    for (int i = 0; i < 4; i++) {
        v[i] = p[tid + i * 128];
        s += v[i];
        s2 += v[i] * v[i];
    }
#pragma unroll
    for (int o = 16; o; o >>= 1) {
        s  += __shfl_xor_sync(0xffffffffu, s,  o);
        s2 += __shfl_xor_sync(0xffffffffu, s2, o);
    }
    __shared__ float ss[4], ss2[4];
    if ((tid & 31) == 0) { ss[tid >> 5] = s; ss2[tid >> 5] = s2; }
    __syncthreads();
    s  = ss[0] + ss[1] + ss[2] + ss[3];
    s2 = ss2[0] + ss2[1] + ss2[2] + ss2[3];
    float m = s * (1.f / DM);
    float var = s2 * (1.f / DM) - m * m;
    float r = rsqrtf(var + 1e-12f);
#pragma unroll
    for (int i = 0; i < 4; i++) {
        int c = tid + i * 128;
        out[(size_t)row * DM + c] = (v[i] - m) * r * g[c] + b[c];
    }
}

// ---------------- launch ------------------------------------------------------
extern "C" void kernel_launch(void* const* d_in, const int* in_sizes, int n_in,
                              void* d_out, int out_size)
{
    const float* x         = (const float*)d_in[0];
    const float* in_proj_w = (const float*)d_in[1];
    const float* conv_w    = (const float*)d_in[2];
    const float* conv_b    = (const float*)d_in[3];
    const float* x_proj_w  = (const float*)d_in[4];
    const float* dt_proj_w = (const float*)d_in[5];
    const float* dt_proj_b = (const float*)d_in[6];
    const float* A_log     = (const float*)d_in[7];
    const float* Dvec      = (const float*)d_in[8];
    const float* out_proj_w= (const float*)d_in[9];
    const float* ln1_g     = (const float*)d_in[10];
    const float* ln1_b     = (const float*)d_in[11];
    const float* fc1_w     = (const float*)d_in[12];
    const float* fc1_b     = (const float*)d_in[13];
    const float* fc2_w     = (const float*)d_in[14];
    const float* fc2_b     = (const float*)d_in[15];
    const float* ln2_g     = (const float*)d_in[16];
    const float* ln2_b     = (const float*)d_in[17];

    float *p_xz, *p_u, *p_xdbl, *p_dt, *p_y, *p_r1, *p_h1, *p_ff, *p_r2;
    cudaGetSymbolAddress((void**)&p_xz,   g_xz);
    cudaGetSymbolAddress((void**)&p_u,    g_u);
    cudaGetSymbolAddress((void**)&p_xdbl, g_xdbl);
    cudaGetSymbolAddress((void**)&p_dt,   g_dt);
    cudaGetSymbolAddress((void**)&p_y,    g_y);
    cudaGetSymbolAddress((void**)&p_r1,   g_r1);
    cudaGetSymbolAddress((void**)&p_h1,   g_h1);
    cudaGetSymbolAddress((void**)&p_ff,   g_ff);
    cudaGetSymbolAddress((void**)&p_r2,   g_r2);

    dim3 blk(16, 16);

    // 1) in_proj: [8192,512] x [2048,512]^T -> g_xz [8192,2048]
    gemm64<0><<<dim3(2 * DI / 64, MROWS / 64), blk>>>(
        x, DM, in_proj_w, DM, nullptr, nullptr, 0, p_xz, 2 * DI);

    // 2) depthwise conv + bias + silu -> g_u
    conv_silu_kernel<<<MROWS * DI / 256, 256>>>(p_xz, conv_w, conv_b, p_u);

    // 3) x_proj: [8192,1024] x [64,1024]^T -> g_xdbl [8192,64]
    gemm64<0><<<dim3(1, MROWS / 64), blk>>>(
        p_u, DI, x_proj_w, DI, nullptr, nullptr, 0, p_xdbl, 64);

    // 4) dt_proj + bias + softplus: [8192,32] x [1024,32]^T -> g_dt [8192,1024]
    gemm64<1><<<dim3(DI / 64, MROWS / 64), blk>>>(
        p_xdbl, 64, dt_proj_w, DTR, dt_proj_b, nullptr, 0, p_dt, DI);

    // 5) selective scan + skip + gate -> g_y
    scan_kernel<<<MROWS * DS / 256, 256>>>(
        p_dt, p_u, p_xdbl, p_xz, A_log, Dvec, p_y);

    // 6) out_proj + residual x -> g_r1 [8192,512]
    gemm64<0><<<dim3(DM / 64, MROWS / 64), blk>>>(
        p_y, DI, out_proj_w, DI, nullptr, x, DM, p_r1, DM);

    // 7) ln1 -> g_h1
    ln512<<<MROWS, 128>>>(p_r1, ln1_g, ln1_b, p_h1);

    // 8) fc1 + bias + gelu -> g_ff [8192,2048]
    gemm64<2><<<dim3(DFF / 64, MROWS / 64), blk>>>(
        p_h1, DM, fc1_w, DM, fc1_b, nullptr, 0, p_ff, DFF);

    // 9) fc2 + bias + residual h1 -> g_r2 [8192,512]
    gemm64<0><<<dim3(DM / 64, MROWS / 64), blk>>>(
        p_ff, DFF, fc2_w, DFF, fc2_b, p_h1, DM, p_r2, DM);

    // 10) ln2 -> out
    ln512<<<MROWS, 128>>>(p_r2, ln2_g, ln2_b, (float*)d_out);
}

// round 5
// speedup vs baseline: 2.5097x; 2.5097x over previous
#include <cuda_runtime.h>
#include <math.h>
#include <stdint.h>

// Problem dims (fixed by reference)
#define BB   8
#define LL   1024
#define DM   512
#define DI   1024
#define DS   16
#define DTR  32
#define DFF  2048
#define MROWS (BB*LL)   // 8192

// ---------------- scratch (static device globals; no allocation) -------------
__device__ float g_xz  [MROWS * 2 * DI];
__device__ float g_u   [MROWS * DI];
__device__ float g_xdbl[MROWS * 64];
__device__ float g_dt  [MROWS * DI];
__device__ float g_y   [MROWS * DI];
__device__ float g_r1  [MROWS * DM];
__device__ float g_h1  [MROWS * DM];
__device__ float g_ff  [MROWS * DFF];
__device__ float g_r2  [MROWS * DM];

// ---------------- helpers ----------------------------------------------------
__device__ __forceinline__ float softplus_f(float x) {
    return x > 20.f ? x : log1pf(expf(x));
}
__device__ __forceinline__ float gelu_f(float x) {
    return 0.5f * x * (1.f + erff(x * 0.70710678118654752f));
}
__device__ __forceinline__ uint32_t f2tf32(float f) {
    uint32_t r;
    asm("cvt.rna.tf32.f32 %0, %1;" : "=r"(r) : "f"(f));
    return r;
}
__device__ __forceinline__ void mma_tf32(float* c, const uint32_t* a, const uint32_t* b) {
    asm volatile(
        "mma.sync.aligned.m16n8k8.row.col.f32.tf32.tf32.f32 "
        "{%0,%1,%2,%3}, {%4,%5,%6,%7}, {%8,%9}, {%0,%1,%2,%3};\n"
        : "+f"(c[0]), "+f"(c[1]), "+f"(c[2]), "+f"(c[3])
        : "r"(a[0]), "r"(a[1]), "r"(a[2]), "r"(a[3]), "r"(b[0]), "r"(b[1]));
}

// ---------------- TF32 tensor-core GEMM: C[M,N] = A[M,K] * W[N,K]^T ----------
// BM=128, BN=128, BK=32, 256 threads (8 warps as 2(M) x 4(N), warp tile 64x32).
// Requires M%128==0, N%128==0, K%32==0.
// Epilogue: bias[col], ACT (0 none, 1 softplus, 2 gelu), residual after act.
template<int ACT>
__global__ void __launch_bounds__(256) gemm_tc(
    const float* __restrict__ A, int lda,
    const float* __restrict__ W, int K,
    const float* __restrict__ bias,
    const float* __restrict__ res, int ldr,
    float* __restrict__ C, int ldc)
{
    __shared__ uint32_t As[128][36];   // [m][k] pad 36 -> conflict-free frag reads
    __shared__ uint32_t Bs[128][36];   // [n][k]

    const int tid  = threadIdx.x;
    const int warp = tid >> 5;
    const int lane = tid & 31;
    const int g    = lane >> 2;        // group 0..7
    const int tg   = lane & 3;         // thread-in-group 0..3
    const int wm   = (warp & 1) * 64;  // warp M offset
    const int wn   = (warp >> 1) * 32; // warp N offset

    const int row0 = blockIdx.y * 128;
    const int col0 = blockIdx.x * 128;

    const int kq = (tid & 7) * 4;      // float4 along k
    const int rr = tid >> 3;           // 0..31

    float acc[4][4][4];
#pragma unroll
    for (int i = 0; i < 4; i++)
#pragma unroll
        for (int j = 0; j < 4; j++)
#pragma unroll
            for (int q = 0; q < 4; q++) acc[i][j][q] = 0.f;

    for (int k0 = 0; k0 < K; k0 += 32) {
        // load A tile 128x32 and B tile 128x32 (coalesced), convert to tf32
#pragma unroll
        for (int i = 0; i < 4; i++) {
            int m = rr + i * 32;
            float4 av = *reinterpret_cast<const float4*>(
                &A[(size_t)(row0 + m) * lda + k0 + kq]);
            uint32_t* dst = &As[m][kq];
            dst[0] = f2tf32(av.x); dst[1] = f2tf32(av.y);
            dst[2] = f2tf32(av.z); dst[3] = f2tf32(av.w);
        }
#pragma unroll
        for (int i = 0; i < 4; i++) {
            int n = rr + i * 32;
            float4 bv = *reinterpret_cast<const float4*>(
                &W[(size_t)(col0 + n) * K + k0 + kq]);
            uint32_t* dst = &Bs[n][kq];
            dst[0] = f2tf32(bv.x); dst[1] = f2tf32(bv.y);
            dst[2] = f2tf32(bv.z); dst[3] = f2tf32(bv.w);
        }
        __syncthreads();

#pragma unroll
        for (int ks = 0; ks < 32; ks += 8) {
            uint32_t af[4][4], bf[4][2];
#pragma unroll
            for (int mf = 0; mf < 4; mf++) {
                int m = wm + mf * 16 + g;
                af[mf][0] = As[m][ks + tg];
                af[mf][1] = As[m + 8][ks + tg];
                af[mf][2] = As[m][ks + tg + 4];
                af[mf][3] = As[m + 8][ks + tg + 4];
            }
#pragma unroll
            for (int nf = 0; nf < 4; nf++) {
                int n = wn + nf * 8 + g;
                bf[nf][0] = Bs[n][ks + tg];
                bf[nf][1] = Bs[n][ks + tg + 4];
            }
#pragma unroll
            for (int mf = 0; mf < 4; mf++)
#pragma unroll
                for (int nf = 0; nf < 4; nf++)
                    mma_tf32(acc[mf][nf], af[mf], bf[nf]);
        }
        __syncthreads();
    }

    // epilogue
#pragma unroll
    for (int mf = 0; mf < 4; mf++) {
        int r0 = row0 + wm + mf * 16 + g;
#pragma unroll
        for (int nf = 0; nf < 4; nf++) {
            int c = col0 + wn + nf * 8 + 2 * tg;
            float v0 = acc[mf][nf][0], v1 = acc[mf][nf][1];
            float v2 = acc[mf][nf][2], v3 = acc[mf][nf][3];
            if (bias) {
                float b0 = bias[c], b1 = bias[c + 1];
                v0 += b0; v1 += b1; v2 += b0; v3 += b1;
            }
            if (ACT == 1) { v0 = softplus_f(v0); v1 = softplus_f(v1);
                            v2 = softplus_f(v2); v3 = softplus_f(v3); }
            if (ACT == 2) { v0 = gelu_f(v0); v1 = gelu_f(v1);
                            v2 = gelu_f(v2); v3 = gelu_f(v3); }
            if (res) {
                v0 += res[(size_t)r0 * ldr + c];
                v1 += res[(size_t)r0 * ldr + c + 1];
                v2 += res[(size_t)(r0 + 8) * ldr + c];
                v3 += res[(size_t)(r0 + 8) * ldr + c + 1];
            }
            *reinterpret_cast<float2*>(&C[(size_t)r0 * ldc + c]) =
                make_float2(v0, v1);
            *reinterpret_cast<float2*>(&C[(size_t)(r0 + 8) * ldc + c]) =
                make_float2(v2, v3);
        }
    }
}

// ---------------- FFMA SGEMM for the small GEMMs (x_proj, dt_proj) -----------
template<int ACT>
__global__ void __launch_bounds__(256) gemm64(
    const float* __restrict__ A, int lda,
    const float* __restrict__ W, int K,
    const float* __restrict__ bias,
    const float* __restrict__ res, int ldr,
    float* __restrict__ C, int ldc)
{
    __shared__ float As[16][68];
    __shared__ float Bs[16][68];

    const int tx = threadIdx.x;
    const int ty = threadIdx.y;
    const int tid = ty * 16 + tx;
    const int row0 = blockIdx.y * 64;
    const int col0 = blockIdx.x * 64;
    const int lk = tid & 15;
    const int lm = tid >> 4;

    float acc[4][4];
#pragma unroll
    for (int i = 0; i < 4; i++)
#pragma unroll
        for (int j = 0; j < 4; j++) acc[i][j] = 0.f;

    for (int k0 = 0; k0 < K; k0 += 16) {
#pragma unroll
        for (int i = 0; i < 4; i++) {
            int m = lm + i * 16;
            As[lk][m] = A[(size_t)(row0 + m) * lda + k0 + lk];
            Bs[lk][m] = W[(size_t)(col0 + m) * K   + k0 + lk];
        }
        __syncthreads();
#pragma unroll
        for (int kk = 0; kk < 16; kk++) {
            float4 a4 = *reinterpret_cast<const float4*>(&As[kk][ty * 4]);
            float4 b4 = *reinterpret_cast<const float4*>(&Bs[kk][tx * 4]);
            float ra[4] = {a4.x, a4.y, a4.z, a4.w};
            float rb[4] = {b4.x, b4.y, b4.z, b4.w};
#pragma unroll
            for (int i = 0; i < 4; i++)
#pragma unroll
                for (int j = 0; j < 4; j++)
                    acc[i][j] += ra[i] * rb[j];
        }
        __syncthreads();
    }

#pragma unroll
    for (int i = 0; i < 4; i++) {
        int r = row0 + ty * 4 + i;
#pragma unroll
        for (int j = 0; j < 4; j++) {
            int c = col0 + tx * 4 + j;
            float v = acc[i][j];
            if (bias) v += bias[c];
            if (ACT == 1) v = softplus_f(v);
            if (ACT == 2) v = gelu_f(v);
            if (res) v += res[(size_t)r * ldr + c];
            C[(size_t)r * ldc + c] = v;
        }
    }
}

// ---------------- causal depthwise conv (width 4) + bias + SiLU --------------
__global__ void conv_silu_kernel(const float* __restrict__ xz,
                                 const float* __restrict__ cw,
                                 const float* __restrict__ cb,
                                 float* __restrict__ u)
{
    int idx = blockIdx.x * blockDim.x + threadIdx.x;
    int d = idx & (DI - 1);
    int row = idx >> 10;
    int l = row & (LL - 1);
    float sum = cb[d];
#pragma unroll
    for (int j = 0; j < 4; j++) {
        int ll = l - 3 + j;
        if (ll >= 0)
            sum += xz[(size_t)(row - 3 + j) * (2 * DI) + d] * cw[d * 4 + j];
    }
    float sig = 1.f / (1.f + __expf(-sum));
    u[idx] = sum * sig;
}

// ---------------- selective scan (1-deep load prefetch pipeline) -------------
__global__ void __launch_bounds__(256) scan_kernel(
    const float* __restrict__ dt, const float* __restrict__ u,
    const float* __restrict__ xdbl, const float* __restrict__ xz,
    const float* __restrict__ A_log, const float* __restrict__ Dp,
    float* __restrict__ y)
{
    int t = blockIdx.x * blockDim.x + threadIdx.x;
    int chain = t >> 4;
    int s = t & 15;
    int b = chain >> 10;
    int d = chain & (DI - 1);

    float a = -expf(A_log[d * DS + s]);
    float Dd = Dp[d];
    float h = 0.f;
    int rb = b << 10;

    size_t base_di = (size_t)rb * DI + d;
    // prime l = 0
    float dt_c = dt[base_di];
    float u_c  = u [base_di];
    float B_c  = xdbl[(rb << 6) + DTR + s];
    float C_c  = xdbl[(rb << 6) + DTR + DS + s];
    float z_c  = (s == 0) ? xz[(size_t)rb * (2 * DI) + DI + d] : 0.f;

    for (int l = 0; l < LL; ++l) {
        float dt_n = 0.f, u_n = 0.f, B_n = 0.f, C_n = 0.f, z_n = 0.f;
        if (l + 1 < LL) {
            size_t bi = base_di + (size_t)(l + 1) * DI;
            dt_n = dt[bi];
            u_n  = u [bi];
            int xi = (rb + l + 1) << 6;
            B_n = xdbl[xi + DTR + s];
            C_n = xdbl[xi + DTR + DS + s];
            if (s == 0) z_n = xz[(size_t)(rb + l + 1) * (2 * DI) + DI + d];
        }

        h = h * __expf(dt_c * a) + (dt_c * B_c) * u_c;
        float p = h * C_c;
        p += __shfl_xor_sync(0xffffffffu, p, 1);
        p += __shfl_xor_sync(0xffffffffu, p, 2);
        p += __shfl_xor_sync(0xffffffffu, p, 4);
        p += __shfl_xor_sync(0xffffffffu, p, 8);
        if (s == 0) {
            float sig = 1.f / (1.f + __expf(-z_c));
            y[(size_t)(rb + l) * DI + d] = (p + u_c * Dd) * (z_c * sig);
        }
        dt_c = dt_n; u_c = u_n; B_c = B_n; C_c = C_n; z_c = z_n;
    }
}

// ---------------- LayerNorm over 512 cols ------------------------------------
__global__ void __launch_bounds__(128) ln512(
    const float* __restrict__ in, const float* __restrict__ g,
    const float* __restrict__ b, float* __restrict__ out)
{
    int row = blockIdx.x;
    const float* p = in + (size_t)row * DM;
    int tid = threadIdx.x;
    float v[4], s = 0.f, s2 = 0.f;
#pragma unroll
    for (int i = 0; i < 4; i++) {
        v[i] = p[tid + i * 128];
        s += v[i];
        s2 += v[i] * v[i];
    }
#pragma unroll
    for (int o = 16; o; o >>= 1) {
        s  += __shfl_xor_sync(0xffffffffu, s,  o);
        s2 += __shfl_xor_sync(0xffffffffu, s2, o);
    }
    __shared__ float ss[4], ss2[4];
    if ((tid & 31) == 0) { ss[tid >> 5] = s; ss2[tid >> 5] = s2; }
    __syncthreads();
    s  = ss[0] + ss[1] + ss[2] + ss[3];
    s2 = ss2[0] + ss2[1] + ss2[2] + ss2[3];
    float m = s * (1.f / DM);
    float var = s2 * (1.f / DM) - m * m;
    float r = rsqrtf(var + 1e-12f);
#pragma unroll
    for (int i = 0; i < 4; i++) {
        int c = tid + i * 128;
        out[(size_t)row * DM + c] = (v[i] - m) * r * g[c] + b[c];
    }
}

// ---------------- launch ------------------------------------------------------
extern "C" void kernel_launch(void* const* d_in, const int* in_sizes, int n_in,
                              void* d_out, int out_size)
{
    const float* x         = (const float*)d_in[0];
    const float* in_proj_w = (const float*)d_in[1];
    const float* conv_w    = (const float*)d_in[2];
    const float* conv_b    = (const float*)d_in[3];
    const float* x_proj_w  = (const float*)d_in[4];
    const float* dt_proj_w = (const float*)d_in[5];
    const float* dt_proj_b = (const float*)d_in[6];
    const float* A_log     = (const float*)d_in[7];
    const float* Dvec      = (const float*)d_in[8];
    const float* out_proj_w= (const float*)d_in[9];
    const float* ln1_g     = (const float*)d_in[10];
    const float* ln1_b     = (const float*)d_in[11];
    const float* fc1_w     = (const float*)d_in[12];
    const float* fc1_b     = (const float*)d_in[13];
    const float* fc2_w     = (const float*)d_in[14];
    const float* fc2_b     = (const float*)d_in[15];
    const float* ln2_g     = (const float*)d_in[16];
    const float* ln2_b     = (const float*)d_in[17];

    float *p_xz, *p_u, *p_xdbl, *p_dt, *p_y, *p_r1, *p_h1, *p_ff, *p_r2;
    cudaGetSymbolAddress((void**)&p_xz,   g_xz);
    cudaGetSymbolAddress((void**)&p_u,    g_u);
    cudaGetSymbolAddress((void**)&p_xdbl, g_xdbl);
    cudaGetSymbolAddress((void**)&p_dt,   g_dt);
    cudaGetSymbolAddress((void**)&p_y,    g_y);
    cudaGetSymbolAddress((void**)&p_r1,   g_r1);
    cudaGetSymbolAddress((void**)&p_h1,   g_h1);
    cudaGetSymbolAddress((void**)&p_ff,   g_ff);
    cudaGetSymbolAddress((void**)&p_r2,   g_r2);

    dim3 blk64(16, 16);

    // 1) in_proj: [8192,512] x [2048,512]^T -> g_xz (TF32 TC)
    gemm_tc<0><<<dim3(2 * DI / 128, MROWS / 128), 256>>>(
        x, DM, in_proj_w, DM, nullptr, nullptr, 0, p_xz, 2 * DI);

    // 2) depthwise conv + bias + silu -> g_u
    conv_silu_kernel<<<MROWS * DI / 256, 256>>>(p_xz, conv_w, conv_b, p_u);

    // 3) x_proj: [8192,1024] x [64,1024]^T -> g_xdbl (FFMA, tiny N)
    gemm64<0><<<dim3(1, MROWS / 64), blk64>>>(
        p_u, DI, x_proj_w, DI, nullptr, nullptr, 0, p_xdbl, 64);

    // 4) dt_proj + softplus: [8192,32] x [1024,32]^T -> g_dt (FFMA, tiny K)
    gemm64<1><<<dim3(DI / 64, MROWS / 64), blk64>>>(
        p_xdbl, 64, dt_proj_w, DTR, dt_proj_b, nullptr, 0, p_dt, DI);

    // 5) selective scan + skip + gate -> g_y
    scan_kernel<<<MROWS * DS / 256, 256>>>(
        p_dt, p_u, p_xdbl, p_xz, A_log, Dvec, p_y);

    // 6) out_proj + residual x -> g_r1 (TF32 TC)
    gemm_tc<0><<<dim3(DM / 128, MROWS / 128), 256>>>(
        p_y, DI, out_proj_w, DI, nullptr, x, DM, p_r1, DM);

    // 7) ln1 -> g_h1
    ln512<<<MROWS, 128>>>(p_r1, ln1_g, ln1_b, p_h1);

    // 8) fc1 + bias + gelu -> g_ff (TF32 TC)
    gemm_tc<2><<<dim3(DFF / 128, MROWS / 128), 256>>>(
        p_h1, DM, fc1_w, DM, fc1_b, nullptr, 0, p_ff, DFF);

    // 9) fc2 + bias + residual h1 -> g_r2 (TF32 TC)
    gemm_tc<0><<<dim3(DM / 128, MROWS / 128), 256>>>(
        p_ff, DFF, fc2_w, DFF, fc2_b, p_h1, DM, p_r2, DM);

    // 10) ln2 -> out
    ln512<<<MROWS, 128>>>(p_r2, ln2_g, ln2_b, (float*)d_out);
}

// round 6
// speedup vs baseline: 2.7575x; 1.0987x over previous
#include <cuda_runtime.h>
#include <math.h>
#include <stdint.h>

// Problem dims (fixed by reference)
#define BB   8
#define LL   1024
#define DM   512
#define DI   1024
#define DS   16
#define DTR  32
#define DFF  2048
#define MROWS (BB*LL)   // 8192

// ---------------- scratch (static device globals; no allocation) -------------
__device__ float g_xz  [MROWS * 2 * DI];
__device__ float g_u   [MROWS * DI];
__device__ float g_xdbl[MROWS * 64];
__device__ float g_dt  [MROWS * DI];
__device__ float g_y   [MROWS * DI];
__device__ float g_r1  [MROWS * DM];
__device__ float g_h1  [MROWS * DM];
__device__ float g_ff  [MROWS * DFF];
__device__ float g_r2  [MROWS * DM];

// ---------------- helpers ----------------------------------------------------
__device__ __forceinline__ float softplus_f(float x) {
    return x > 20.f ? x : log1pf(expf(x));
}
__device__ __forceinline__ float gelu_f(float x) {
    return 0.5f * x * (1.f + erff(x * 0.70710678118654752f));
}
__device__ __forceinline__ void mma_tf32(float* c, const uint32_t* a, const uint32_t* b) {
    asm volatile(
        "mma.sync.aligned.m16n8k8.row.col.f32.tf32.tf32.f32 "
        "{%0,%1,%2,%3}, {%4,%5,%6,%7}, {%8,%9}, {%0,%1,%2,%3};\n"
        : "+f"(c[0]), "+f"(c[1]), "+f"(c[2]), "+f"(c[3])
        : "r"(a[0]), "r"(a[1]), "r"(a[2]), "r"(a[3]), "r"(b[0]), "r"(b[1]));
}
__device__ __forceinline__ void cp_async16(void* smem, const void* gmem) {
    uint32_t s = (uint32_t)__cvta_generic_to_shared(smem);
    asm volatile("cp.async.cg.shared.global [%0], [%1], 16;\n" :: "r"(s), "l"(gmem));
}
__device__ __forceinline__ void cp_commit() {
    asm volatile("cp.async.commit_group;\n");
}
template<int N>
__device__ __forceinline__ void cp_wait() {
    asm volatile("cp.async.wait_group %0;\n" :: "n"(N));
}

// ---------------- TF32 tensor-core GEMM: C[M,N] = A[M,K] * W[N,K]^T ----------
// BM=128, BN in {128, 64}, BK=32, 256 threads, cp.async double-buffered.
// Raw fp32 bits in smem; mma.tf32 truncates to tf32 (rz).
// BN=128: 8 warps as 2(M)x4(N), warp tile 64x32 (MF=4).
// BN= 64: 8 warps as 4(M)x2(N), warp tile 32x32 (MF=2).
// Epilogue: bias[col], ACT (0 none, 1 softplus, 2 gelu), residual after act.
template<int ACT, int BN>
__global__ void __launch_bounds__(256) gemm_tc(
    const float* __restrict__ A, int lda,
    const float* __restrict__ W, int K,
    const float* __restrict__ bias,
    const float* __restrict__ res, int ldr,
    float* __restrict__ C, int ldc)
{
    constexpr int MF = (BN == 128) ? 4 : 2;
    extern __shared__ uint32_t sm[];
    uint32_t (*As)[128][36] = reinterpret_cast<uint32_t(*)[128][36]>(sm);
    uint32_t (*Bs)[BN][36]  = reinterpret_cast<uint32_t(*)[BN][36]>(sm + 2 * 128 * 36);

    const int tid  = threadIdx.x;
    const int warp = tid >> 5;
    const int lane = tid & 31;
    const int g    = lane >> 2;
    const int tg   = lane & 3;
    const int wm   = (BN == 128) ? (warp & 1) * 64 : (warp & 3) * 32;
    const int wn   = (BN == 128) ? (warp >> 1) * 32 : (warp >> 2) * 32;

    const int row0 = blockIdx.y * 128;
    const int col0 = blockIdx.x * BN;

    const int kq = (tid & 7) * 4;      // float4 along k
    const int rr = tid >> 3;           // 0..31

    float acc[MF][4][4];
#pragma unroll
    for (int i = 0; i < MF; i++)
#pragma unroll
        for (int j = 0; j < 4; j++)
#pragma unroll
            for (int q = 0; q < 4; q++) acc[i][j][q] = 0.f;

    const int T = K / 32;

    // prefetch stage 0
    {
#pragma unroll
        for (int i = 0; i < 4; i++) {
            int m = rr + i * 32;
            cp_async16(&As[0][m][kq], &A[(size_t)(row0 + m) * lda + kq]);
        }
#pragma unroll
        for (int i = 0; i < BN / 32; i++) {
            int n = rr + i * 32;
            cp_async16(&Bs[0][n][kq], &W[(size_t)(col0 + n) * K + kq]);
        }
        cp_commit();
    }

    for (int kt = 0; kt < T; kt++) {
        if (kt + 1 < T) {
            int st = (kt + 1) & 1;
            int k0 = (kt + 1) * 32;
#pragma unroll
            for (int i = 0; i < 4; i++) {
                int m = rr + i * 32;
                cp_async16(&As[st][m][kq], &A[(size_t)(row0 + m) * lda + k0 + kq]);
            }
#pragma unroll
            for (int i = 0; i < BN / 32; i++) {
                int n = rr + i * 32;
                cp_async16(&Bs[st][n][kq], &W[(size_t)(col0 + n) * K + k0 + kq]);
            }
            cp_commit();
            cp_wait<1>();
        } else {
            cp_wait<0>();
        }
        __syncthreads();

        const int st = kt & 1;
#pragma unroll
        for (int ks = 0; ks < 32; ks += 8) {
            uint32_t af[MF][4], bf[4][2];
#pragma unroll
            for (int mf = 0; mf < MF; mf++) {
                int m = wm + mf * 16 + g;
                af[mf][0] = As[st][m][ks + tg];
                af[mf][1] = As[st][m + 8][ks + tg];
                af[mf][2] = As[st][m][ks + tg + 4];
                af[mf][3] = As[st][m + 8][ks + tg + 4];
            }
#pragma unroll
            for (int nf = 0; nf < 4; nf++) {
                int n = wn + nf * 8 + g;
                bf[nf][0] = Bs[st][n][ks + tg];
                bf[nf][1] = Bs[st][n][ks + tg + 4];
            }
#pragma unroll
            for (int mf = 0; mf < MF; mf++)
#pragma unroll
                for (int nf = 0; nf < 4; nf++)
                    mma_tf32(acc[mf][nf], af[mf], bf[nf]);
        }
        __syncthreads();
    }

    // epilogue
#pragma unroll
    for (int mf = 0; mf < MF; mf++) {
        int r0 = row0 + wm + mf * 16 + g;
#pragma unroll
        for (int nf = 0; nf < 4; nf++) {
            int c = col0 + wn + nf * 8 + 2 * tg;
            float v0 = acc[mf][nf][0], v1 = acc[mf][nf][1];
            float v2 = acc[mf][nf][2], v3 = acc[mf][nf][3];
            if (bias) {
                float b0 = bias[c], b1 = bias[c + 1];
                v0 += b0; v1 += b1; v2 += b0; v3 += b1;
            }
            if (ACT == 1) { v0 = softplus_f(v0); v1 = softplus_f(v1);
                            v2 = softplus_f(v2); v3 = softplus_f(v3); }
            if (ACT == 2) { v0 = gelu_f(v0); v1 = gelu_f(v1);
                            v2 = gelu_f(v2); v3 = gelu_f(v3); }
            if (res) {
                v0 += res[(size_t)r0 * ldr + c];
                v1 += res[(size_t)r0 * ldr + c + 1];
                v2 += res[(size_t)(r0 + 8) * ldr + c];
                v3 += res[(size_t)(r0 + 8) * ldr + c + 1];
            }
            *reinterpret_cast<float2*>(&C[(size_t)r0 * ldc + c]) =
                make_float2(v0, v1);
            *reinterpret_cast<float2*>(&C[(size_t)(r0 + 8) * ldc + c]) =
                make_float2(v2, v3);
        }
    }
}

// ---------------- causal depthwise conv (width 4) + bias + SiLU --------------
__global__ void conv_silu_kernel(const float* __restrict__ xz,
                                 const float* __restrict__ cw,
                                 const float* __restrict__ cb,
                                 float* __restrict__ u)
{
    int idx = blockIdx.x * blockDim.x + threadIdx.x;
    int d = idx & (DI - 1);
    int row = idx >> 10;
    int l = row & (LL - 1);
    float sum = cb[d];
#pragma unroll
    for (int j = 0; j < 4; j++) {
        int ll = l - 3 + j;
        if (ll >= 0)
            sum += xz[(size_t)(row - 3 + j) * (2 * DI) + d] * cw[d * 4 + j];
    }
    float sig = 1.f / (1.f + __expf(-sum));
    u[idx] = sum * sig;
}

// ---------------- selective scan (1-deep load prefetch pipeline) -------------
__global__ void __launch_bounds__(256) scan_kernel(
    const float* __restrict__ dt, const float* __restrict__ u,
    const float* __restrict__ xdbl, const float* __restrict__ xz,
    const float* __restrict__ A_log, const float* __restrict__ Dp,
    float* __restrict__ y)
{
    int t = blockIdx.x * blockDim.x + threadIdx.x;
    int chain = t >> 4;
    int s = t & 15;
    int b = chain >> 10;
    int d = chain & (DI - 1);

    float a = -expf(A_log[d * DS + s]);
    float Dd = Dp[d];
    float h = 0.f;
    int rb = b << 10;

    size_t base_di = (size_t)rb * DI + d;
    float dt_c = dt[base_di];
    float u_c  = u [base_di];
    float B_c  = xdbl[(rb << 6) + DTR + s];
    float C_c  = xdbl[(rb << 6) + DTR + DS + s];
    float z_c  = (s == 0) ? xz[(size_t)rb * (2 * DI) + DI + d] : 0.f;

    for (int l = 0; l < LL; ++l) {
        float dt_n = 0.f, u_n = 0.f, B_n = 0.f, C_n = 0.f, z_n = 0.f;
        if (l + 1 < LL) {
            size_t bi = base_di + (size_t)(l + 1) * DI;
            dt_n = dt[bi];
            u_n  = u [bi];
            int xi = (rb + l + 1) << 6;
            B_n = xdbl[xi + DTR + s];
            C_n = xdbl[xi + DTR + DS + s];
            if (s == 0) z_n = xz[(size_t)(rb + l + 1) * (2 * DI) + DI + d];
        }

        h = h * __expf(dt_c * a) + (dt_c * B_c) * u_c;
        float p = h * C_c;
        p += __shfl_xor_sync(0xffffffffu, p, 1);
        p += __shfl_xor_sync(0xffffffffu, p, 2);
        p += __shfl_xor_sync(0xffffffffu, p, 4);
        p += __shfl_xor_sync(0xffffffffu, p, 8);
        if (s == 0) {
            float sig = 1.f / (1.f + __expf(-z_c));
            y[(size_t)(rb + l) * DI + d] = (p + u_c * Dd) * (z_c * sig);
        }
        dt_c = dt_n; u_c = u_n; B_c = B_n; C_c = C_n; z_c = z_n;
    }
}

// ---------------- LayerNorm over 512 cols ------------------------------------
__global__ void __launch_bounds__(128) ln512(
    const float* __restrict__ in, const float* __restrict__ g,
    const float* __restrict__ b, float* __restrict__ out)
{
    int row = blockIdx.x;
    const float* p = in + (size_t)row * DM;
    int tid = threadIdx.x;
    float v[4], s = 0.f, s2 = 0.f;
#pragma unroll
    for (int i = 0; i < 4; i++) {
        v[i] = p[tid + i * 128];
        s += v[i];
        s2 += v[i] * v[i];
    }
#pragma unroll
    for (int o = 16; o; o >>= 1) {
        s  += __shfl_xor_sync(0xffffffffu, s,  o);
        s2 += __shfl_xor_sync(0xffffffffu, s2, o);
    }
    __shared__ float ss[4], ss2[4];
    if ((tid & 31) == 0) { ss[tid >> 5] = s; ss2[tid >> 5] = s2; }
    __syncthreads();
    s  = ss[0] + ss[1] + ss[2] + ss[3];
    s2 = ss2[0] + ss2[1] + ss2[2] + ss2[3];
    float m = s * (1.f / DM);
    float var = s2 * (1.f / DM) - m * m;
    float r = rsqrtf(var + 1e-12f);
#pragma unroll
    for (int i = 0; i < 4; i++) {
        int c = tid + i * 128;
        out[(size_t)row * DM + c] = (v[i] - m) * r * g[c] + b[c];
    }
}

// ---------------- launch ------------------------------------------------------
extern "C" void kernel_launch(void* const* d_in, const int* in_sizes, int n_in,
                              void* d_out, int out_size)
{
    const float* x         = (const float*)d_in[0];
    const float* in_proj_w = (const float*)d_in[1];
    const float* conv_w    = (const float*)d_in[2];
    const float* conv_b    = (const float*)d_in[3];
    const float* x_proj_w  = (const float*)d_in[4];
    const float* dt_proj_w = (const float*)d_in[5];
    const float* dt_proj_b = (const float*)d_in[6];
    const float* A_log     = (const float*)d_in[7];
    const float* Dvec      = (const float*)d_in[8];
    const float* out_proj_w= (const float*)d_in[9];
    const float* ln1_g     = (const float*)d_in[10];
    const float* ln1_b     = (const float*)d_in[11];
    const float* fc1_w     = (const float*)d_in[12];
    const float* fc1_b     = (const float*)d_in[13];
    const float* fc2_w     = (const float*)d_in[14];
    const float* fc2_b     = (const float*)d_in[15];
    const float* ln2_g     = (const float*)d_in[16];
    const float* ln2_b     = (const float*)d_in[17];

    float *p_xz, *p_u, *p_xdbl, *p_dt, *p_y, *p_r1, *p_h1, *p_ff, *p_r2;
    cudaGetSymbolAddress((void**)&p_xz,   g_xz);
    cudaGetSymbolAddress((void**)&p_u,    g_u);
    cudaGetSymbolAddress((void**)&p_xdbl, g_xdbl);
    cudaGetSymbolAddress((void**)&p_dt,   g_dt);
    cudaGetSymbolAddress((void**)&p_y,    g_y);
    cudaGetSymbolAddress((void**)&p_r1,   g_r1);
    cudaGetSymbolAddress((void**)&p_h1,   g_h1);
    cudaGetSymbolAddress((void**)&p_ff,   g_ff);
    cudaGetSymbolAddress((void**)&p_r2,   g_r2);

    const int smem128 = (2 * 128 * 36 + 2 * 128 * 36) * 4;  // 73728 B
    const int smem64  = (2 * 128 * 36 + 2 *  64 * 36) * 4;  // 55296 B

    cudaFuncSetAttribute(gemm_tc<0,128>, cudaFuncAttributeMaxDynamicSharedMemorySize, smem128);
    cudaFuncSetAttribute(gemm_tc<1,128>, cudaFuncAttributeMaxDynamicSharedMemorySize, smem128);
    cudaFuncSetAttribute(gemm_tc<2,128>, cudaFuncAttributeMaxDynamicSharedMemorySize, smem128);
    cudaFuncSetAttribute(gemm_tc<0,64>,  cudaFuncAttributeMaxDynamicSharedMemorySize, smem64);

    // 1) in_proj: [8192,512] x [2048,512]^T -> g_xz
    gemm_tc<0,128><<<dim3(2 * DI / 128, MROWS / 128), 256, smem128>>>(
        x, DM, in_proj_w, DM, nullptr, nullptr, 0, p_xz, 2 * DI);

    // 2) depthwise conv + bias + silu -> g_u
    conv_silu_kernel<<<MROWS * DI / 256, 256>>>(p_xz, conv_w, conv_b, p_u);

    // 3) x_proj: [8192,1024] x [64,1024]^T -> g_xdbl
    gemm_tc<0,64><<<dim3(1, MROWS / 128), 256, smem64>>>(
        p_u, DI, x_proj_w, DI, nullptr, nullptr, 0, p_xdbl, 64);

    // 4) dt_proj + softplus: [8192,32] x [1024,32]^T -> g_dt
    gemm_tc<1,128><<<dim3(DI / 128, MROWS / 128), 256, smem128>>>(
        p_xdbl, 64, dt_proj_w, DTR, dt_proj_b, nullptr, 0, p_dt, DI);

    // 5) selective scan + skip + gate -> g_y
    scan_kernel<<<MROWS * DS / 256, 256>>>(
        p_dt, p_u, p_xdbl, p_xz, A_log, Dvec, p_y);

    // 6) out_proj + residual x -> g_r1
    gemm_tc<0,128><<<dim3(DM / 128, MROWS / 128), 256, smem128>>>(
        p_y, DI, out_proj_w, DI, nullptr, x, DM, p_r1, DM);

    // 7) ln1 -> g_h1
    ln512<<<MROWS, 128>>>(p_r1, ln1_g, ln1_b, p_h1);

    // 8) fc1 + bias + gelu -> g_ff
    gemm_tc<2,128><<<dim3(DFF / 128, MROWS / 128), 256, smem128>>>(
        p_h1, DM, fc1_w, DM, fc1_b, nullptr, 0, p_ff, DFF);

    // 9) fc2 + bias + residual h1 -> g_r2
    gemm_tc<0,128><<<dim3(DM / 128, MROWS / 128), 256, smem128>>>(
        p_ff, DFF, fc2_w, DFF, fc2_b, p_h1, DM, p_r2, DM);

    // 10) ln2 -> out
    ln512<<<MROWS, 128>>>(p_r2, ln2_g, ln2_b, (float*)d_out);
}